// round 16
// baseline (speedup 1.0000x reference)
#include <cuda_runtime.h>
#include <cuda_bf16.h>

// Soft-PQ via warp-level HMMA (mma.sync m16n8k16 bf16), hi/lo 3-MMA fp32 emulation.
// logit_k = (2*<x,c_k> - |c_k|^2)/T  (x^2 cancels in softmax).
// R16: PASS-MAJOR MMA ORDER — same-accumulator reuse distance 2 -> 8 MMAs,
// killing the RAW short-scoreboard stall that capped tensor at ~35%.
// B ping-pong pipeline, warp-coop recon, survivor lists kept. 2 CTAs/SM.

#define KCW 256
#define DM  128
#define TILE_M 64
#define CAP 64            // survivor list capacity per row (expected ~3)

// ---- smem byte offsets ----
#define OFF_XH  0         // 17408: X stage hi (64 rows x 272B); lists after GEMM
#define OFF_XL  17408     // 17408: X stage lo
#define OFF_C2  34816     // 1024:  c2 * invT (256 f)
#define OFF_STM 35840     // 1024:  max partials [wc*64+row]
#define OFF_CNT 36864     // 256:   survivor counters (64 u32)
#define SMEM_TOTAL 37120
#define XSTRIDE 272       // bytes per staged X row (136 bf16)

// B fragment image, hi+lo fused per entry:
// index = wc*2048 + kt*256 + j*32 + lane   (uint4: .x,.y = bh, .z,.w = bl)
__device__ __align__(16) uint4 g_bf[8][8192];
__device__ float g_c2[8 * KCW];

__device__ __forceinline__ void mma_bf16(float* d, const unsigned* a,
                                         unsigned bx, unsigned by) {
    asm volatile(
        "mma.sync.aligned.m16n8k16.row.col.f32.bf16.bf16.f32 "
        "{%0,%1,%2,%3}, {%4,%5,%6,%7}, {%8,%9}, {%0,%1,%2,%3};"
        : "+f"(d[0]), "+f"(d[1]), "+f"(d[2]), "+f"(d[3])
        : "r"(a[0]), "r"(a[1]), "r"(a[2]), "r"(a[3]), "r"(bx), "r"(by));
}

// ======================= prep kernel =======================
// Bakes codebook into fused hi/lo bf16 HMMA B-fragment image + c2.
// m16n8k16 col-major B frag: lane q=lane%4, g=lane/4; n = nt*8+g;
// reg.x = {k=kt*16+q*2, +1}, reg.y = {+8, +9}.   nt = wc*8 + j.
__global__ void prep_kernel(const float* __restrict__ cb) {
    int m = blockIdx.x, by = blockIdx.y, tid = threadIdx.x;
    if (by == 0) {
        const float* src = cb + ((size_t)m * KCW + tid) * DM;
        float c2 = 0.0f;
        for (int d4 = 0; d4 < DM; d4 += 4) {
            float4 v = *(const float4*)(src + d4);
            c2 = fmaf(v.x, v.x, c2); c2 = fmaf(v.y, v.y, c2);
            c2 = fmaf(v.z, v.z, c2); c2 = fmaf(v.w, v.w, c2);
        }
        g_c2[m * KCW + tid] = c2;
    }
#pragma unroll
    for (int i = 0; i < 8; ++i) {
        int e = by * 2048 + i * 256 + tid;
        int lane = e & 31, j = (e >> 5) & 7, kt = (e >> 8) & 7, wc = (e >> 11) & 3;
        int q = lane & 3, g = lane >> 2;
        int n = (wc * 8 + j) * 8 + g;
        int k0 = kt * 16 + q * 2;
        const float* src = cb + ((size_t)m * KCW + n) * DM;
        float f[4] = { src[k0], src[k0 + 1], src[k0 + 8], src[k0 + 9] };
        unsigned h[4], l[4];
#pragma unroll
        for (int u = 0; u < 4; ++u) {
            __nv_bfloat16 hb = __float2bfloat16_rn(f[u]);
            __nv_bfloat16 lb = __float2bfloat16_rn(f[u] - __bfloat162float(hb));
            h[u] = __bfloat16_as_ushort(hb);
            l[u] = __bfloat16_as_ushort(lb);
        }
        g_bf[m][e] = make_uint4(h[0] | (h[1] << 16), h[2] | (h[3] << 16),
                                l[0] | (l[1] << 16), l[2] | (l[3] << 16));
    }
}

// ======================= main kernel =======================
__global__ void __launch_bounds__(256, 2)
softpq_hmma_kernel(const float* __restrict__ x,
                   const float* __restrict__ cb,
                   const void* __restrict__ tptr,
                   float* __restrict__ out,
                   int N)
{
    extern __shared__ char smem[];
    const int tid  = threadIdx.x;
    const int wid  = tid >> 5;
    const int lane = tid & 31;
    const int q    = lane & 3;
    const int g    = lane >> 2;
    const int wr   = wid & 1;    // rows wr*32 .. wr*32+31
    const int wc   = wid >> 1;   // cols wc*64 .. wc*64+63
    const int m    = blockIdx.y;
    const int row0 = blockIdx.x * TILE_M;

    // temperature (robust to int32/float32 scalar encodings)
    float temp;
    {
        float tf = *(const float*)tptr;
        if (tf >= 1e-6f && tf <= 1e6f) temp = tf;
        else { int ti = *(const int*)tptr; temp = (ti != 0) ? (float)ti : 1.0f; }
    }
    const float inv_temp = 1.0f / temp;
    const float two_it = 2.0f * inv_temp;

    const uint4* pB = g_bf[m] + wc * 2048 + lane;

    // --- pipeline prologue: first B half-chunk in flight BEFORE X staging ---
    uint4 b0[4], b1[4];
#pragma unroll
    for (int j = 0; j < 4; ++j) b0[j] = __ldg(pB + j * 32);

    // survivor counters zeroed early (visible after the pre-GEMM syncthreads)
    if (tid < 64) ((unsigned*)(smem + OFF_CNT))[tid] = 0u;

    // --- X tile: coalesced load, hi/lo bf16 split, stage (272B row stride) ---
    {
#pragma unroll
        for (int it = 0; it < 8; ++it) {
            int f = tid + it * 256;           // float4 index
            int r = f >> 5, c4 = f & 31;      // whole warp on one row
            int gr = row0 + r;
            float4 v = make_float4(0.f, 0.f, 0.f, 0.f);
            if (gr < N)
                v = *(const float4*)(x + (size_t)gr * 1024 + m * DM + c4 * 4);
            float fv[4] = { v.x, v.y, v.z, v.w };
            unsigned h[4], l[4];
#pragma unroll
            for (int u = 0; u < 4; ++u) {
                __nv_bfloat16 hb = __float2bfloat16_rn(fv[u]);
                __nv_bfloat16 lb = __float2bfloat16_rn(fv[u] - __bfloat162float(hb));
                h[u] = __bfloat16_as_ushort(hb);
                l[u] = __bfloat16_as_ushort(lb);
            }
            *(uint2*)(smem + OFF_XH + r * XSTRIDE + c4 * 8) =
                make_uint2(h[0] | (h[1] << 16), h[2] | (h[3] << 16));
            *(uint2*)(smem + OFF_XL + r * XSTRIDE + c4 * 8) =
                make_uint2(l[0] | (l[1] << 16), l[2] | (l[3] << 16));
        }
    }

    // --- c2 * invT ---
    ((float*)(smem + OFF_C2))[tid] = g_c2[m * KCW + tid] * inv_temp;
    __syncthreads();           // X stage + counters visible

    // --- fused, software-pipelined HMMA GEMM (pass-major MMA order) ---
    float acc[2][8][4];
#pragma unroll
    for (int mt = 0; mt < 2; ++mt)
#pragma unroll
        for (int j = 0; j < 8; ++j)
#pragma unroll
            for (int u = 0; u < 4; ++u) acc[mt][j][u] = 0.0f;

    const char* AbH = smem + OFF_XH + (wr * 32 + g) * XSTRIDE + q * 4;
    const char* AbL = smem + OFF_XL + (wr * 32 + g) * XSTRIDE + q * 4;

#pragma unroll 1
    for (int kt = 0; kt < 8; ++kt) {
        // issue b1 <- (kt, j=4..7) before touching b0
#pragma unroll
        for (int j = 0; j < 4; ++j) b1[j] = __ldg(pB + kt * 256 + 128 + j * 32);

        // A frags (hi + lo) from smem, once per kt
        unsigned ah[2][4], al[2][4];
#pragma unroll
        for (int mt = 0; mt < 2; ++mt) {
            const char* hp = AbH + mt * (16 * XSTRIDE) + kt * 32;
            const char* lp = AbL + mt * (16 * XSTRIDE) + kt * 32;
            ah[mt][0] = *(const unsigned*)(hp);
            ah[mt][1] = *(const unsigned*)(hp + 8 * XSTRIDE);
            ah[mt][2] = *(const unsigned*)(hp + 16);
            ah[mt][3] = *(const unsigned*)(hp + 8 * XSTRIDE + 16);
            al[mt][0] = *(const unsigned*)(lp);
            al[mt][1] = *(const unsigned*)(lp + 8 * XSTRIDE);
            al[mt][2] = *(const unsigned*)(lp + 16);
            al[mt][3] = *(const unsigned*)(lp + 8 * XSTRIDE + 16);
        }

        // half 0 (b0, j=0..3): pass-major — each acc touched every 8 MMAs
#pragma unroll
        for (int j = 0; j < 4; ++j) {
            mma_bf16(acc[0][j], ah[0], b0[j].x, b0[j].y);
            mma_bf16(acc[1][j], ah[1], b0[j].x, b0[j].y);
        }
#pragma unroll
        for (int j = 0; j < 4; ++j) {
            mma_bf16(acc[0][j], al[0], b0[j].x, b0[j].y);
            mma_bf16(acc[1][j], al[1], b0[j].x, b0[j].y);
        }
#pragma unroll
        for (int j = 0; j < 4; ++j) {
            mma_bf16(acc[0][j], ah[0], b0[j].z, b0[j].w);
            mma_bf16(acc[1][j], ah[1], b0[j].z, b0[j].w);
        }

        // issue b0 <- (kt+1, j=0..3) while b1's MMAs run (kt=7: dummy reload)
        int ktn = (kt < 7) ? kt + 1 : 7;
#pragma unroll
        for (int j = 0; j < 4; ++j) b0[j] = __ldg(pB + ktn * 256 + j * 32);

        // half 1 (b1, j=4..7): pass-major
#pragma unroll
        for (int j = 0; j < 4; ++j) {
            mma_bf16(acc[0][4 + j], ah[0], b1[j].x, b1[j].y);
            mma_bf16(acc[1][4 + j], ah[1], b1[j].x, b1[j].y);
        }
#pragma unroll
        for (int j = 0; j < 4; ++j) {
            mma_bf16(acc[0][4 + j], al[0], b1[j].x, b1[j].y);
            mma_bf16(acc[1][4 + j], al[1], b1[j].x, b1[j].y);
        }
#pragma unroll
        for (int j = 0; j < 4; ++j) {
            mma_bf16(acc[0][4 + j], ah[0], b1[j].z, b1[j].w);
            mma_bf16(acc[1][4 + j], ah[1], b1[j].z, b1[j].w);
        }
    }

    // --- logits in registers + per-row quarter-MAX to smem ---
    {
        const float* c2s = (const float*)(smem + OFF_C2);
        float c2v[8][2];
#pragma unroll
        for (int j = 0; j < 8; ++j) {
            int col = wc * 64 + j * 8 + q * 2;
            c2v[j][0] = c2s[col];
            c2v[j][1] = c2s[col + 1];
        }
#pragma unroll
        for (int mt = 0; mt < 2; ++mt)
#pragma unroll
            for (int j = 0; j < 8; ++j) {
                acc[mt][j][0] = fmaf(acc[mt][j][0], two_it, -c2v[j][0]);
                acc[mt][j][1] = fmaf(acc[mt][j][1], two_it, -c2v[j][1]);
                acc[mt][j][2] = fmaf(acc[mt][j][2], two_it, -c2v[j][0]);
                acc[mt][j][3] = fmaf(acc[mt][j][3], two_it, -c2v[j][1]);
            }

        float* stm = (float*)(smem + OFF_STM);
#pragma unroll
        for (int mt = 0; mt < 2; ++mt)
#pragma unroll
            for (int rh = 0; rh < 2; ++rh) {
                float mv = -3.402823466e38f;
#pragma unroll
                for (int j = 0; j < 8; ++j) {
                    mv = fmaxf(mv, acc[mt][j][rh * 2 + 0]);
                    mv = fmaxf(mv, acc[mt][j][rh * 2 + 1]);
                }
                mv = fmaxf(mv, __shfl_xor_sync(0xffffffffu, mv, 1));
                mv = fmaxf(mv, __shfl_xor_sync(0xffffffffu, mv, 2));
                if (q == 0) stm[wc * 64 + (wr * 32 + mt * 16 + rh * 8 + g)] = mv;
            }
    }
    __syncthreads();   // stm complete; X-stage reads done -> region reusable as lists

    // --- survivor append: exp only within 16.6 of global row max ---
    // (dropped mass <= 1.6e-5 of S)
    {
        const float* stm = (const float*)(smem + OFF_STM);
        unsigned* cnt = (unsigned*)(smem + OFF_CNT);
        uint2* list = (uint2*)(smem + OFF_XH);
#pragma unroll
        for (int mt = 0; mt < 2; ++mt)
#pragma unroll
            for (int rh = 0; rh < 2; ++rh) {
                int row = wr * 32 + mt * 16 + rh * 8 + g;
                float M = fmaxf(fmaxf(stm[row], stm[64 + row]),
                                fmaxf(stm[128 + row], stm[192 + row]));
                float cut = M - 16.6f;
#pragma unroll
                for (int j = 0; j < 8; ++j) {
#pragma unroll
                    for (int u = 0; u < 2; ++u) {
                        float l = acc[mt][j][rh * 2 + u];
                        if (l > cut) {
                            unsigned idx = atomicAdd(&cnt[row], 1u);
                            if (idx < CAP) {
                                unsigned k = (unsigned)(wc * 64 + j * 8 + q * 2 + u);
                                list[row * CAP + idx] =
                                    make_uint2(k, __float_as_uint(__expf(l - M)));
                            }
                        }
                    }
                }
            }
    }
    __syncthreads();

    // --- warp-cooperative reconstruction: warp wid owns rows wid*8..wid*8+7 ---
    {
        const unsigned* cnt = (const unsigned*)(smem + OFF_CNT);
        const uint2* list = (const uint2*)(smem + OFF_XH);
        const float* Cm = cb + (size_t)m * KCW * DM;

#pragma unroll 1
        for (int rr = 0; rr < 8; ++rr) {
            int row = wid * 8 + rr;
            int n = (int)cnt[row];
            if (n > CAP) n = CAP;
            const uint2* lrow = list + row * CAP;

            // S: lanes read list entries in parallel, warp-reduce
            float s = 0.0f;
            if (lane < n) s = __uint_as_float(lrow[lane].y);
            if (n > 32 && lane + 32 < n) s += __uint_as_float(lrow[lane + 32].y);
#pragma unroll
            for (int off = 16; off > 0; off >>= 1)
                s += __shfl_xor_sync(0xffffffffu, s, off);
            const float invS = 1.0f / s;

            float4 o = make_float4(0.f, 0.f, 0.f, 0.f);
#pragma unroll 2
            for (int i = 0; i < n; ++i) {
                uint2 ent = lrow[i];            // broadcast LDS
                float p = __uint_as_float(ent.y) * invS;
                float4 c = __ldg((const float4*)(Cm + (size_t)ent.x * DM) + lane);
                o.x = fmaf(p, c.x, o.x);
                o.y = fmaf(p, c.y, o.y);
                o.z = fmaf(p, c.z, o.z);
                o.w = fmaf(p, c.w, o.w);
            }

            int gr = row0 + row;
            if (gr < N)
                *((float4*)(out + (size_t)gr * 1024 + m * DM) + lane) = o;
        }
    }
}

extern "C" void kernel_launch(void* const* d_in, const int* in_sizes, int n_in,
                              void* d_out, int out_size)
{
    const float* x  = (const float*)d_in[0];
    const float* cb = (const float*)d_in[1];
    const void*  t  = d_in[2];
    float* out = (float*)d_out;

    int N = in_sizes[0] / 1024;   // D = M*D_M = 1024

    prep_kernel<<<dim3(8, 4), 256>>>(cb);

    cudaFuncSetAttribute(softpq_hmma_kernel,
                         cudaFuncAttributeMaxDynamicSharedMemorySize, SMEM_TOTAL);
    dim3 grid((N + TILE_M - 1) / TILE_M, 8);
    softpq_hmma_kernel<<<grid, 256, SMEM_TOTAL>>>(x, cb, t, out, N);
}

// round 17
// speedup vs baseline: 1.0930x; 1.0930x over previous
#include <cuda_runtime.h>
#include <cuda_bf16.h>

// Soft-PQ via warp-level HMMA (mma.sync m16n8k16 bf16), hi/lo 3-MMA fp32 emulation.
// logit_k = (2*<x,c_k> - |c_k|^2)/T  (x^2 cancels in softmax).
// R17: RE-TILE FOR OCCUPANCY — warp tile 32x64 -> 32x32 (acc 64 -> 32 regs),
// CTA = 32 rows x 256 cols, launch_bounds(256,3) => 3 CTAs/SM, 24 warps (+50%
// latency hiding; R16 showed the kernel is uniformly latency-bound at 16 warps).
// B direct-from-global ping-pong, survivor lists, warp-coop recon kept.

#define KCW 256
#define DM  128
#define TILE_M 32
#define CAP 64            // survivor list capacity per row (expected ~3)

// ---- smem byte offsets ----
#define OFF_XH  0         // 8704: X stage hi (32 rows x 272B); lists after GEMM
#define OFF_XL  8704      // 8704: X stage lo
#define OFF_C2  17408     // 1024: c2 * invT (256 f)
#define OFF_STM 18432     // 1024: max partials [w*32+row] (8 warps x 32 rows)
#define OFF_CNT 19456     // 128:  survivor counters (32 u32)
#define SMEM_TOTAL 19584
#define XSTRIDE 272       // bytes per staged X row (136 bf16)

// B fragment image, per-warp chunks, hi+lo fused per entry:
// index = w*1024 + kt*128 + j*32 + lane   (uint4: .x,.y = bh, .z,.w = bl)
// n-tile nt = w*4 + j  (cols nt*8..nt*8+7)
__device__ __align__(16) uint4 g_bf[8][8192];
__device__ float g_c2[8 * KCW];

__device__ __forceinline__ void mma_bf16(float* d, const unsigned* a,
                                         unsigned bx, unsigned by) {
    asm volatile(
        "mma.sync.aligned.m16n8k16.row.col.f32.bf16.bf16.f32 "
        "{%0,%1,%2,%3}, {%4,%5,%6,%7}, {%8,%9}, {%0,%1,%2,%3};"
        : "+f"(d[0]), "+f"(d[1]), "+f"(d[2]), "+f"(d[3])
        : "r"(a[0]), "r"(a[1]), "r"(a[2]), "r"(a[3]), "r"(bx), "r"(by));
}

// ======================= prep kernel =======================
// Bakes codebook into fused hi/lo bf16 HMMA B-fragment image + c2.
// m16n8k16 col-major B frag: lane q=lane%4, g=lane/4; n = nt*8+g;
// reg.x = {k=kt*16+q*2, +1}, reg.y = {+8, +9}.   nt = w*4 + j.
__global__ void prep_kernel(const float* __restrict__ cb) {
    int m = blockIdx.x, by = blockIdx.y, tid = threadIdx.x;
    if (by == 0) {
        const float* src = cb + ((size_t)m * KCW + tid) * DM;
        float c2 = 0.0f;
        for (int d4 = 0; d4 < DM; d4 += 4) {
            float4 v = *(const float4*)(src + d4);
            c2 = fmaf(v.x, v.x, c2); c2 = fmaf(v.y, v.y, c2);
            c2 = fmaf(v.z, v.z, c2); c2 = fmaf(v.w, v.w, c2);
        }
        g_c2[m * KCW + tid] = c2;
    }
#pragma unroll
    for (int i = 0; i < 8; ++i) {
        int e = by * 2048 + i * 256 + tid;
        int lane = e & 31, j = (e >> 5) & 3, kt = (e >> 7) & 7, w = (e >> 10) & 7;
        int q = lane & 3, g = lane >> 2;
        int n = (w * 4 + j) * 8 + g;
        int k0 = kt * 16 + q * 2;
        const float* src = cb + ((size_t)m * KCW + n) * DM;
        float f[4] = { src[k0], src[k0 + 1], src[k0 + 8], src[k0 + 9] };
        unsigned h[4], l[4];
#pragma unroll
        for (int u = 0; u < 4; ++u) {
            __nv_bfloat16 hb = __float2bfloat16_rn(f[u]);
            __nv_bfloat16 lb = __float2bfloat16_rn(f[u] - __bfloat162float(hb));
            h[u] = __bfloat16_as_ushort(hb);
            l[u] = __bfloat16_as_ushort(lb);
        }
        g_bf[m][e] = make_uint4(h[0] | (h[1] << 16), h[2] | (h[3] << 16),
                                l[0] | (l[1] << 16), l[2] | (l[3] << 16));
    }
}

// ======================= main kernel =======================
__global__ void __launch_bounds__(256, 3)
softpq_hmma_kernel(const float* __restrict__ x,
                   const float* __restrict__ cb,
                   const void* __restrict__ tptr,
                   float* __restrict__ out,
                   int N)
{
    extern __shared__ char smem[];
    const int tid  = threadIdx.x;
    const int wid  = tid >> 5;   // warp owns cols wid*32 .. wid*32+31, all 32 rows
    const int lane = tid & 31;
    const int q    = lane & 3;
    const int g    = lane >> 2;
    const int m    = blockIdx.y;
    const int row0 = blockIdx.x * TILE_M;

    // temperature (robust to int32/float32 scalar encodings)
    float temp;
    {
        float tf = *(const float*)tptr;
        if (tf >= 1e-6f && tf <= 1e6f) temp = tf;
        else { int ti = *(const int*)tptr; temp = (ti != 0) ? (float)ti : 1.0f; }
    }
    const float inv_temp = 1.0f / temp;
    const float two_it = 2.0f * inv_temp;

    const uint4* pB = g_bf[m] + wid * 1024 + lane;

    // --- pipeline prologue: first B pair in flight BEFORE X staging ---
    uint4 b0[2], b1[2];
#pragma unroll
    for (int j = 0; j < 2; ++j) b0[j] = __ldg(pB + j * 32);

    // survivor counters zeroed early
    if (tid < 32) ((unsigned*)(smem + OFF_CNT))[tid] = 0u;

    // --- X tile: coalesced load, hi/lo bf16 split, stage (272B row stride) ---
    {
#pragma unroll
        for (int it = 0; it < 4; ++it) {
            int f = tid + it * 256;           // float4 index (0..1023)
            int r = f >> 5, c4 = f & 31;      // whole warp on one row
            int gr = row0 + r;
            float4 v = make_float4(0.f, 0.f, 0.f, 0.f);
            if (gr < N)
                v = *(const float4*)(x + (size_t)gr * 1024 + m * DM + c4 * 4);
            float fv[4] = { v.x, v.y, v.z, v.w };
            unsigned h[4], l[4];
#pragma unroll
            for (int u = 0; u < 4; ++u) {
                __nv_bfloat16 hb = __float2bfloat16_rn(fv[u]);
                __nv_bfloat16 lb = __float2bfloat16_rn(fv[u] - __bfloat162float(hb));
                h[u] = __bfloat16_as_ushort(hb);
                l[u] = __bfloat16_as_ushort(lb);
            }
            *(uint2*)(smem + OFF_XH + r * XSTRIDE + c4 * 8) =
                make_uint2(h[0] | (h[1] << 16), h[2] | (h[3] << 16));
            *(uint2*)(smem + OFF_XL + r * XSTRIDE + c4 * 8) =
                make_uint2(l[0] | (l[1] << 16), l[2] | (l[3] << 16));
        }
    }

    // --- c2 * invT ---
    ((float*)(smem + OFF_C2))[tid] = g_c2[m * KCW + tid] * inv_temp;
    __syncthreads();           // X stage + counters visible

    // --- fused, software-pipelined HMMA GEMM ---
    float acc[2][4][4];
#pragma unroll
    for (int mt = 0; mt < 2; ++mt)
#pragma unroll
        for (int j = 0; j < 4; ++j)
#pragma unroll
            for (int u = 0; u < 4; ++u) acc[mt][j][u] = 0.0f;

    const char* AbH = smem + OFF_XH + g * XSTRIDE + q * 4;
    const char* AbL = smem + OFF_XL + g * XSTRIDE + q * 4;

#pragma unroll 1
    for (int kt = 0; kt < 8; ++kt) {
        // issue b1 <- (kt, j=2..3) before touching b0
#pragma unroll
        for (int j = 0; j < 2; ++j) b1[j] = __ldg(pB + kt * 128 + 64 + j * 32);

        // A frags (hi + lo) from smem, once per kt; rows mt*16+g, mt*16+g+8
        unsigned ah[2][4], al[2][4];
#pragma unroll
        for (int mt = 0; mt < 2; ++mt) {
            const char* hp = AbH + mt * (16 * XSTRIDE) + kt * 32;
            const char* lp = AbL + mt * (16 * XSTRIDE) + kt * 32;
            ah[mt][0] = *(const unsigned*)(hp);
            ah[mt][1] = *(const unsigned*)(hp + 8 * XSTRIDE);
            ah[mt][2] = *(const unsigned*)(hp + 16);
            ah[mt][3] = *(const unsigned*)(hp + 8 * XSTRIDE + 16);
            al[mt][0] = *(const unsigned*)(lp);
            al[mt][1] = *(const unsigned*)(lp + 8 * XSTRIDE);
            al[mt][2] = *(const unsigned*)(lp + 16);
            al[mt][3] = *(const unsigned*)(lp + 8 * XSTRIDE + 16);
        }

        // 12 MMAs on b0 (j = 0..1) while b1 is in flight
#pragma unroll
        for (int j = 0; j < 2; ++j) {
            mma_bf16(acc[0][j], ah[0], b0[j].x, b0[j].y);
            mma_bf16(acc[1][j], ah[1], b0[j].x, b0[j].y);
            mma_bf16(acc[0][j], al[0], b0[j].x, b0[j].y);
            mma_bf16(acc[1][j], al[1], b0[j].x, b0[j].y);
            mma_bf16(acc[0][j], ah[0], b0[j].z, b0[j].w);
            mma_bf16(acc[1][j], ah[1], b0[j].z, b0[j].w);
        }

        // issue b0 <- (kt+1, j=0..1) while b1's MMAs run (kt=7: dummy reload)
        int ktn = (kt < 7) ? kt + 1 : 7;
#pragma unroll
        for (int j = 0; j < 2; ++j) b0[j] = __ldg(pB + ktn * 128 + j * 32);

        // 12 MMAs on b1 (j = 2..3)
#pragma unroll
        for (int j = 0; j < 2; ++j) {
            mma_bf16(acc[0][2 + j], ah[0], b1[j].x, b1[j].y);
            mma_bf16(acc[1][2 + j], ah[1], b1[j].x, b1[j].y);
            mma_bf16(acc[0][2 + j], al[0], b1[j].x, b1[j].y);
            mma_bf16(acc[1][2 + j], al[1], b1[j].x, b1[j].y);
            mma_bf16(acc[0][2 + j], ah[0], b1[j].z, b1[j].w);
            mma_bf16(acc[1][2 + j], ah[1], b1[j].z, b1[j].w);
        }
    }

    // --- logits in registers + per-(warp,row) MAX partials to smem ---
    {
        const float* c2s = (const float*)(smem + OFF_C2);
        float c2v[4][2];
#pragma unroll
        for (int j = 0; j < 4; ++j) {
            int col = wid * 32 + j * 8 + q * 2;
            c2v[j][0] = c2s[col];
            c2v[j][1] = c2s[col + 1];
        }
#pragma unroll
        for (int mt = 0; mt < 2; ++mt)
#pragma unroll
            for (int j = 0; j < 4; ++j) {
                acc[mt][j][0] = fmaf(acc[mt][j][0], two_it, -c2v[j][0]);
                acc[mt][j][1] = fmaf(acc[mt][j][1], two_it, -c2v[j][1]);
                acc[mt][j][2] = fmaf(acc[mt][j][2], two_it, -c2v[j][0]);
                acc[mt][j][3] = fmaf(acc[mt][j][3], two_it, -c2v[j][1]);
            }

        float* stm = (float*)(smem + OFF_STM);
#pragma unroll
        for (int mt = 0; mt < 2; ++mt)
#pragma unroll
            for (int rh = 0; rh < 2; ++rh) {
                float mv = -3.402823466e38f;
#pragma unroll
                for (int j = 0; j < 4; ++j) {
                    mv = fmaxf(mv, acc[mt][j][rh * 2 + 0]);
                    mv = fmaxf(mv, acc[mt][j][rh * 2 + 1]);
                }
                mv = fmaxf(mv, __shfl_xor_sync(0xffffffffu, mv, 1));
                mv = fmaxf(mv, __shfl_xor_sync(0xffffffffu, mv, 2));
                if (q == 0) stm[wid * 32 + (mt * 16 + rh * 8 + g)] = mv;
            }
    }
    __syncthreads();   // stm complete; X-stage reads done -> region reusable as lists

    // --- survivor append: exp only within 16.6 of global row max ---
    // (dropped mass <= 1.6e-5 of S)
    {
        const float* stm = (const float*)(smem + OFF_STM);
        unsigned* cnt = (unsigned*)(smem + OFF_CNT);
        uint2* list = (uint2*)(smem + OFF_XH);
#pragma unroll
        for (int mt = 0; mt < 2; ++mt)
#pragma unroll
            for (int rh = 0; rh < 2; ++rh) {
                int row = mt * 16 + rh * 8 + g;
                float M = stm[row];
#pragma unroll
                for (int w = 1; w < 8; ++w) M = fmaxf(M, stm[w * 32 + row]);
                float cut = M - 16.6f;
#pragma unroll
                for (int j = 0; j < 4; ++j) {
#pragma unroll
                    for (int u = 0; u < 2; ++u) {
                        float l = acc[mt][j][rh * 2 + u];
                        if (l > cut) {
                            unsigned idx = atomicAdd(&cnt[row], 1u);
                            if (idx < CAP) {
                                unsigned k = (unsigned)(wid * 32 + j * 8 + q * 2 + u);
                                list[row * CAP + idx] =
                                    make_uint2(k, __float_as_uint(__expf(l - M)));
                            }
                        }
                    }
                }
            }
    }
    __syncthreads();

    // --- warp-cooperative reconstruction: warp wid owns rows wid*4..wid*4+3 ---
    {
        const unsigned* cnt = (const unsigned*)(smem + OFF_CNT);
        const uint2* list = (const uint2*)(smem + OFF_XH);
        const float* Cm = cb + (size_t)m * KCW * DM;

#pragma unroll 1
        for (int rr = 0; rr < 4; ++rr) {
            int row = wid * 4 + rr;
            int n = (int)cnt[row];
            if (n > CAP) n = CAP;
            const uint2* lrow = list + row * CAP;

            // S: lanes read list entries in parallel, warp-reduce
            float s = 0.0f;
            if (lane < n) s = __uint_as_float(lrow[lane].y);
            if (n > 32 && lane + 32 < n) s += __uint_as_float(lrow[lane + 32].y);
#pragma unroll
            for (int off = 16; off > 0; off >>= 1)
                s += __shfl_xor_sync(0xffffffffu, s, off);
            const float invS = 1.0f / s;

            float4 o = make_float4(0.f, 0.f, 0.f, 0.f);
#pragma unroll 2
            for (int i = 0; i < n; ++i) {
                uint2 ent = lrow[i];            // broadcast LDS
                float p = __uint_as_float(ent.y) * invS;
                float4 c = __ldg((const float4*)(Cm + (size_t)ent.x * DM) + lane);
                o.x = fmaf(p, c.x, o.x);
                o.y = fmaf(p, c.y, o.y);
                o.z = fmaf(p, c.z, o.z);
                o.w = fmaf(p, c.w, o.w);
            }

            int gr = row0 + row;
            if (gr < N)
                *((float4*)(out + (size_t)gr * 1024 + m * DM) + lane) = o;
        }
    }
}

extern "C" void kernel_launch(void* const* d_in, const int* in_sizes, int n_in,
                              void* d_out, int out_size)
{
    const float* x  = (const float*)d_in[0];
    const float* cb = (const float*)d_in[1];
    const void*  t  = d_in[2];
    float* out = (float*)d_out;

    int N = in_sizes[0] / 1024;   // D = M*D_M = 1024

    prep_kernel<<<dim3(8, 4), 256>>>(cb);

    cudaFuncSetAttribute(softpq_hmma_kernel,
                         cudaFuncAttributeMaxDynamicSharedMemorySize, SMEM_TOTAL);
    dim3 grid((N + TILE_M - 1) / TILE_M, 8);
    softpq_hmma_kernel<<<grid, 256, SMEM_TOTAL>>>(x, cb, t, out, N);
}